// round 2
// baseline (speedup 1.0000x reference)
#include <cuda_runtime.h>

#define N_NODES 100000
#define DIM 64
#define R 5
#define E 500000

// Scratch: per-relation aggregated features (aggregate-first formulation).
// 2 x 128 MB static device arrays (allowed; no runtime allocation).
__device__ __align__(16) float g_s_u[(size_t)R * N_NODES * DIM];
__device__ __align__(16) float g_s_v[(size_t)R * N_NODES * DIM];
__device__ __align__(16) float g_Wc_u[R * DIM * DIM];
__device__ __align__(16) float g_Wc_v[R * DIM * DIM];

// ---------------------------------------------------------------------------
// Zero the scatter accumulators (256 MB total), float4 grid-stride.
// ---------------------------------------------------------------------------
__global__ void zero_s_kernel() {
    const size_t n4 = (size_t)R * N_NODES * DIM / 4;
    float4* a = reinterpret_cast<float4*>(g_s_u);
    float4* b = reinterpret_cast<float4*>(g_s_v);
    const float4 z = make_float4(0.f, 0.f, 0.f, 0.f);
    for (size_t i = (size_t)blockIdx.x * blockDim.x + threadIdx.x; i < n4;
         i += (size_t)gridDim.x * blockDim.x) {
        a[i] = z;
        b[i] = z;
    }
}

// ---------------------------------------------------------------------------
// Cumulative (ordinal mixture) weights: Wc[r] = sum_{j<=r} W[j]. 4096 threads.
// ---------------------------------------------------------------------------
__global__ void cumsum_kernel(const float* __restrict__ wu,
                              const float* __restrict__ wv) {
    int t = blockIdx.x * blockDim.x + threadIdx.x;
    if (t >= DIM * DIM) return;
    float a = 0.f, b = 0.f;
#pragma unroll
    for (int r = 0; r < R; r++) {
        a += wu[r * DIM * DIM + t];
        b += wv[r * DIM * DIM + t];
        g_Wc_u[r * DIM * DIM + t] = a;
        g_Wc_v[r * DIM * DIM + t] = b;
    }
}

// ---------------------------------------------------------------------------
// Edge scatter: one warp per edge, both directions in the same warp.
// lanes 0-15 : s_u[r, edge_u] += val * x_v[edge_v]   (float4 per lane)
// lanes 16-31: s_v[r, edge_v] += val * x_u[edge_u]
// Gather sources (x_u, x_v = 51 MB) stay L2-resident; scatter uses 16B vector
// reductions (red.global.add.v4.f32) to quarter the L2 atomic op count.
// ---------------------------------------------------------------------------
__global__ __launch_bounds__(256) void scatter_kernel(
    const float* __restrict__ x_u, const float* __restrict__ x_v,
    const float* __restrict__ edge_val, const int* __restrict__ edge_u,
    const int* __restrict__ edge_v) {
    long gw = ((long)blockIdx.x * blockDim.x + threadIdx.x) >> 5;
    if (gw >= (long)R * E) return;
    const int lane = threadIdx.x & 31;

    const float val = __ldg(edge_val + gw);
    const int u = __ldg(edge_u + gw);
    const int v = __ldg(edge_v + gw);
    const int r = (int)(gw / E);
    const int q = lane & 15;

    const float* src;
    float* dst;
    if (lane < 16) {
        src = x_v + (long)v * DIM;
        dst = g_s_u + ((long)r * N_NODES + u) * DIM;
    } else {
        src = x_u + (long)u * DIM;
        dst = g_s_v + ((long)r * N_NODES + v) * DIM;
    }

    float4 p = *reinterpret_cast<const float4*>(src + q * 4);
    p.x *= val;
    p.y *= val;
    p.z *= val;
    p.w *= val;
    asm volatile("red.global.add.v4.f32 [%0], {%1,%2,%3,%4};" ::"l"(dst + q * 4),
                 "f"(p.x), "f"(p.y), "f"(p.z), "f"(p.w)
                 : "memory");
}

// ---------------------------------------------------------------------------
// Output GEMM: out[n,o] = relu(bias[o] + sum_r sum_d s[r,n,d] * Wc[r,d,o]).
// Block = 256 threads, tile = 128 nodes x 64 outputs. Thread tile 4x8 using
// packed fma.rn.f32x2 (2 FMAs/inst) with the weight pair loaded directly as
// a 64-bit shared load (contiguous outputs) and the s value broadcast-packed.
// blockIdx.y selects direction (0: users, 1: items).
// ---------------------------------------------------------------------------
__global__ __launch_bounds__(256) void output_gemm_kernel(
    const float* __restrict__ bias_u, const float* __restrict__ bias_v,
    float* __restrict__ out) {
    __shared__ float s_sh[128 * DIM];  // 32 KB
    __shared__ float w_sh[DIM * DIM];  // 16 KB

    const int dir = blockIdx.y;
    const float* __restrict__ S = dir ? g_s_v : g_s_u;
    const float* __restrict__ W = dir ? g_Wc_u : g_Wc_v;  // z_u uses Wv, z_v uses Wu
    const float* __restrict__ bias = dir ? bias_v : bias_u;
    float* o_base = out + (size_t)dir * N_NODES * DIM;

    const int nbase = blockIdx.x * 128;
    const int tid = threadIdx.x;
    const int oid = tid & 7;   // 8 output groups of 8
    const int o0 = oid * 8;
    const int nid = tid >> 3;  // 32 node groups of 4

    unsigned long long acc[4][4];
#pragma unroll
    for (int n = 0; n < 4; n++)
#pragma unroll
        for (int p = 0; p < 4; p++) acc[n][p] = 0ull;  // packed {0.f, 0.f}

    for (int r = 0; r < R; r++) {
        // Stage weight slice (64x64) into shared.
        const float4* Wg = reinterpret_cast<const float4*>(W + r * DIM * DIM);
        float4* w4 = reinterpret_cast<float4*>(w_sh);
#pragma unroll
        for (int k = 0; k < 4; k++) w4[tid + k * 256] = Wg[tid + k * 256];

        // Stage s tile (128 x 64) into shared, coalesced float4, guarded.
        const float* Sg = S + (size_t)r * N_NODES * DIM;
        float4* s4 = reinterpret_cast<float4*>(s_sh);
#pragma unroll
        for (int k = 0; k < 8; k++) {
            int i = tid + k * 256;
            int row = i >> 4;
            int c = i & 15;
            int gn = nbase + row;
            float4 vv = make_float4(0.f, 0.f, 0.f, 0.f);
            if (gn < N_NODES)
                vv = reinterpret_cast<const float4*>(Sg + (size_t)gn * DIM)[c];
            s4[i] = vv;
        }
        __syncthreads();

#pragma unroll 8
        for (int d = 0; d < DIM; d++) {
            const unsigned long long* wp =
                reinterpret_cast<const unsigned long long*>(w_sh + d * DIM + o0);
            unsigned long long w0 = wp[0], w1 = wp[1], w2 = wp[2], w3 = wp[3];
#pragma unroll
            for (int n = 0; n < 4; n++) {
                float s = s_sh[(nid * 4 + n) * DIM + d];
                unsigned long long sp;
                asm("mov.b64 %0, {%1, %1};" : "=l"(sp) : "f"(s));
                asm("fma.rn.f32x2 %0, %1, %2, %0;" : "+l"(acc[n][0]) : "l"(w0), "l"(sp));
                asm("fma.rn.f32x2 %0, %1, %2, %0;" : "+l"(acc[n][1]) : "l"(w1), "l"(sp));
                asm("fma.rn.f32x2 %0, %1, %2, %0;" : "+l"(acc[n][2]) : "l"(w2), "l"(sp));
                asm("fma.rn.f32x2 %0, %1, %2, %0;" : "+l"(acc[n][3]) : "l"(w3), "l"(sp));
            }
        }
        __syncthreads();
    }

    float bsv[8];
#pragma unroll
    for (int j = 0; j < 8; j++) bsv[j] = __ldg(bias + o0 + j);

#pragma unroll
    for (int n = 0; n < 4; n++) {
        int gn = nbase + nid * 4 + n;
        if (gn >= N_NODES) continue;
        float res[8];
#pragma unroll
        for (int p = 0; p < 4; p++) {
            float lo, hi;
            asm("mov.b64 {%0,%1}, %2;" : "=f"(lo), "=f"(hi) : "l"(acc[n][p]));
            res[2 * p] = lo;
            res[2 * p + 1] = hi;
        }
#pragma unroll
        for (int j = 0; j < 8; j++) {
            float x = res[j] + bsv[j];
            res[j] = x > 0.f ? x : 0.f;
        }
        float4* op = reinterpret_cast<float4*>(o_base + (size_t)gn * DIM + o0);
        op[0] = make_float4(res[0], res[1], res[2], res[3]);
        op[1] = make_float4(res[4], res[5], res[6], res[7]);
    }
}

// ---------------------------------------------------------------------------
// Launch: zero -> cumsum -> scatter -> gemm (same stream, implicit ordering).
// ---------------------------------------------------------------------------
extern "C" void kernel_launch(void* const* d_in, const int* in_sizes, int n_in,
                              void* d_out, int out_size) {
    const float* x_u = (const float*)d_in[0];
    const float* x_v = (const float*)d_in[1];
    const float* w_u = (const float*)d_in[2];
    const float* w_v = (const float*)d_in[3];
    const float* bias_u = (const float*)d_in[4];
    const float* bias_v = (const float*)d_in[5];
    const float* edge_val = (const float*)d_in[6];
    const int* edge_u = (const int*)d_in[7];
    const int* edge_v = (const int*)d_in[8];
    float* out = (float*)d_out;

    zero_s_kernel<<<4096, 256>>>();
    cumsum_kernel<<<16, 256>>>(w_u, w_v);

    long total_threads = (long)R * E * 32;
    int blocks = (int)((total_threads + 255) / 256);  // 312500
    scatter_kernel<<<blocks, 256>>>(x_u, x_v, edge_val, edge_u, edge_v);

    dim3 grid((N_NODES + 127) / 128, 2);
    output_gemm_kernel<<<grid, 256>>>(bias_u, bias_v, out);
}